// round 15
// baseline (speedup 1.0000x reference)
#include <cuda_runtime.h>
#include <cuda_bf16.h>

// ---------------------------------------------------------------------------
// TGAT restructured (math unchanged).
//   fold_qk(1) -> gemm1(2) -> fold_ov(3) -> attn(4, profiled slot) ->
//   gemm2(5) -> LN(6) -> ffn1(7) -> ffn2(8)
//   gemm1: 128x128-cf FFMA2 single-buffer, concat A-load, split-K=2 (384 CTAs)
//   attn : flash, 1 warp/batch, packed f32x2, launch_bounds(128,5) to force
//          regs<=102 (occupancy 5 CTAs/SM); sums 2 qk slabs in q-load
//   gemm2: 128x128-cf FFMA2 single-buffer, split-K=3 (288 CTAs)
//   LN   : sums 3 slabs + bo
//   ffn1 : 128x64 FFMA2 split-K=4 ; ffn2: 64x64 FFMA2, 4-slab A-combine
// ---------------------------------------------------------------------------

#define Bsz 4096
typedef unsigned long long ull;

__device__ __align__(16) float g_wqk[768 * 256];
__device__ __align__(16) float g_wov[384 * 768];
__device__ __align__(16) float g_qk [2 * Bsz * 768];   // 2 split-K slabs
__device__ __align__(16) float g_ctx[Bsz * 768];
__device__ __align__(16) float g_out[3 * Bsz * 384];   // split-K=3 slabs
__device__ __align__(16) float g_x  [Bsz * 512];
__device__ __align__(16) float g_h  [4 * Bsz * 128];   // split-K=4 slabs

#define FFMA2(d, a, b) \
    asm("fma.rn.f32x2 %0, %1, %2, %0;" : "+l"(d) : "l"(a), "l"(b))
#define MUL2(d, a, b) \
    asm("mul.rn.f32x2 %0, %1, %2;" : "=l"(d) : "l"(a), "l"(b))
__device__ __forceinline__ ull dupf(float x) {
    ull d;
    unsigned r = __float_as_uint(x);
    asm("mov.b64 %0, {%1, %1};" : "=l"(d) : "r"(r));
    return d;
}
__device__ __forceinline__ float lo32(ull v) { return __uint_as_float((unsigned)v); }
__device__ __forceinline__ float hi32(ull v) { return __uint_as_float((unsigned)(v >> 32)); }

// ---------------------------------------------------------------------------
// Fold 1: Wqk[r, c] = sum_d Wk[h*192+d, mloc] * Wq[h*192+d, m'(c)]
// ---------------------------------------------------------------------------
__global__ void fold_qk_kernel(const float* __restrict__ Wk,
                               const float* __restrict__ Wq,
                               float* __restrict__ Wqk)
{
    __shared__ float sA[16][16];
    __shared__ float sB[16][16];
    int tx = threadIdx.x, ty = threadIdx.y;
    int bid = blockIdx.x;
    int c0 = (bid & 15) * 16;
    int r0 = (bid >> 4) * 16;
    int h    = r0 / 384;
    int mloc = r0 % 384;
    int c = c0 + tx;
    int mprime = (c < 128) ? c : c + 128;
    float acc = 0.f;
    for (int dt = 0; dt < 192; dt += 16) {
        int d = h * 192 + dt + ty;
        sA[ty][tx] = Wk[d * 384 + (mloc + tx)];
        sB[ty][tx] = Wq[d * 384 + mprime];
        __syncthreads();
        #pragma unroll
        for (int kk = 0; kk < 16; kk++)
            acc = fmaf(sA[kk][ty], sB[kk][tx], acc);
        __syncthreads();
    }
    Wqk[(r0 + ty) * 256 + c0 + tx] = acc;
}

// ---------------------------------------------------------------------------
// Fold 2: Wov[j, c] = sum_d Wo[j, h*192+d] * Wv[h*192+d, m0]  (runs 3rd)
// ---------------------------------------------------------------------------
__global__ void fold_ov_kernel(const float* __restrict__ Wo,
                               const float* __restrict__ Wv,
                               float* __restrict__ Wov)
{
    __shared__ float sA[16][16];
    __shared__ float sB[16][16];
    int tx = threadIdx.x, ty = threadIdx.y;
    int bid = blockIdx.x;
    int c0 = (bid % 48) * 16;
    int r0 = (bid / 48) * 16;
    int h  = c0 / 384;
    int m0 = c0 % 384;
    float acc = 0.f;
    for (int dt = 0; dt < 192; dt += 16) {
        sA[ty][tx] = Wo[(r0 + ty) * 384 + (h * 192 + dt + tx)];
        sB[ty][tx] = Wv[(h * 192 + dt + ty) * 384 + (m0 + tx)];
        __syncthreads();
        #pragma unroll
        for (int kk = 0; kk < 16; kk++)
            acc = fmaf(sA[ty][kk], sB[kk][tx], acc);
        __syncthreads();
    }
    Wov[(r0 + ty) * 768 + c0 + tx] = acc;
}

// ---------------------------------------------------------------------------
// fp32 NT GEMM: 128x64 tile, BK=16, 256 threads, 8x4 micro, FFMA2,
// double-buffered. Concat mode via A1. Split-K via gridDim.z. (FFN1.)
// ---------------------------------------------------------------------------
__global__ void gemm_nt_128x64(const float* __restrict__ A0,
                               const float* __restrict__ A1,
                               const float* __restrict__ B,
                               float* __restrict__ C,
                               int M, int N, int K)
{
    __shared__ float As[2][16][128];
    __shared__ float Bs[2][16][64];
    const int tid  = threadIdx.x;
    const int row0 = blockIdx.y * 128;
    const int col0 = blockIdx.x * 64;
    const int Kslice = K / gridDim.z;
    const int kbase  = blockIdx.z * Kslice;
    float* Cz = C + (size_t)blockIdx.z * (size_t)M * N;

    const int arow  = tid >> 1;
    const int akoff = (tid & 1) << 3;
    const int brow  = tid >> 2;
    const int bkoff = (tid & 3) << 2;
    const float* Bp = B + (long)(col0 + brow) * K + kbase + bkoff;

    const int tr = (tid >> 4) << 3;
    const int tc = (tid & 15) << 2;

    ull accp[4][4] = {};

    float4 a0, a1, b0;

    auto loadA = [&](int k) {
        int kk = kbase + k + akoff;
        long row = row0 + arow;
        const float* p;
        if (A1) p = (kk < 128) ? (A0 + row * 128 + kk)
                               : (A1 + row * 128 + (kk - 128));
        else    p = A0 + row * (long)K + kk;
        a0 = *(const float4*)p;
        a1 = *(const float4*)(p + 4);
    };
    auto loadB = [&](int k) { b0 = *(const float4*)(Bp + k); };
    auto stAB = [&](int buf) {
        As[buf][akoff + 0][arow] = a0.x; As[buf][akoff + 1][arow] = a0.y;
        As[buf][akoff + 2][arow] = a0.z; As[buf][akoff + 3][arow] = a0.w;
        As[buf][akoff + 4][arow] = a1.x; As[buf][akoff + 5][arow] = a1.y;
        As[buf][akoff + 6][arow] = a1.z; As[buf][akoff + 7][arow] = a1.w;
        Bs[buf][bkoff + 0][brow] = b0.x; Bs[buf][bkoff + 1][brow] = b0.y;
        Bs[buf][bkoff + 2][brow] = b0.z; Bs[buf][bkoff + 3][brow] = b0.w;
    };

    loadA(0); loadB(0);
    stAB(0);
    __syncthreads();

    int buf = 0;
    for (int k0 = 0; k0 < Kslice; k0 += 16) {
        const bool nxt = (k0 + 16) < Kslice;
        if (nxt) { loadA(k0 + 16); loadB(k0 + 16); }
        #pragma unroll
        for (int kk = 0; kk < 16; kk++) {
            ull rap[4];
            *(float4*)(&rap[0]) = *(const float4*)&As[buf][kk][tr];
            *(float4*)(&rap[2]) = *(const float4*)&As[buf][kk][tr + 4];
            float4 rbv = *(const float4*)&Bs[buf][kk][tc];
            ull bd0 = dupf(rbv.x), bd1 = dupf(rbv.y);
            ull bd2 = dupf(rbv.z), bd3 = dupf(rbv.w);
            #pragma unroll
            for (int p = 0; p < 4; p++) {
                FFMA2(accp[p][0], rap[p], bd0);
                FFMA2(accp[p][1], rap[p], bd1);
                FFMA2(accp[p][2], rap[p], bd2);
                FFMA2(accp[p][3], rap[p], bd3);
            }
        }
        if (nxt) {
            buf ^= 1;
            stAB(buf);
            __syncthreads();
        }
    }

    #pragma unroll
    for (int p = 0; p < 4; p++) {
        long r0r = row0 + tr + 2 * p;
        float o0[4], o1[4];
        #pragma unroll
        for (int j = 0; j < 4; j++) {
            o0[j] = lo32(accp[p][j]);
            o1[j] = hi32(accp[p][j]);
        }
        *(float4*)(Cz + r0r * N + col0 + tc)       = *(float4*)(o0);
        *(float4*)(Cz + (r0r + 1) * N + col0 + tc) = *(float4*)(o1);
    }
}

// ---------------------------------------------------------------------------
// fp32 NT GEMM: 128x128 tile, BK=16, 256 threads, 8x8 micro, FFMA2,
// single-buffered, occ-2, conflict-free B reads (16B lane stride).
// Concat mode via A1. Split-K via gridDim.z.
// ---------------------------------------------------------------------------
__global__ void __launch_bounds__(256, 2)
gemm_nt_128x128(const float* __restrict__ A0, const float* __restrict__ A1,
                const float* __restrict__ B, float* __restrict__ C,
                int M, int N, int K)
{
    __shared__ float As[16][128];
    __shared__ float Bs[16][128];
    const int tid  = threadIdx.x;
    const int row0 = blockIdx.y * 128;
    const int col0 = blockIdx.x * 128;
    const int Kslice = K / gridDim.z;
    const int kbase  = blockIdx.z * Kslice;
    float* Cz = C + (size_t)blockIdx.z * (size_t)M * N;

    const int lrow = tid >> 1;
    const int koff = (tid & 1) << 3;
    const int tr = (tid >> 4) << 3;
    const int tc = (tid & 15) << 2;      // 16B stride: conflict-free

    ull accp[4][8] = {};   // j 0-3: cols tc+j ; j 4-7: cols 64+tc+(j-4)

    const float* Bp = B + (long)(col0 + lrow) * K + kbase + koff;
    const long arowg = row0 + lrow;

    for (int k0 = 0; k0 < Kslice; k0 += 16) {
        float4 a0, a1, b0, b1;
        {
            int kk = kbase + k0 + koff;
            const float* p;
            if (A1) p = (kk < 128) ? (A0 + arowg * 128 + kk)
                                   : (A1 + arowg * 128 + (kk - 128));
            else    p = A0 + arowg * (long)K + kk;
            a0 = *(const float4*)p;
            a1 = *(const float4*)(p + 4);
            b0 = *(const float4*)(Bp + k0);
            b1 = *(const float4*)(Bp + k0 + 4);
        }
        __syncthreads();
        As[koff + 0][lrow] = a0.x; As[koff + 1][lrow] = a0.y;
        As[koff + 2][lrow] = a0.z; As[koff + 3][lrow] = a0.w;
        As[koff + 4][lrow] = a1.x; As[koff + 5][lrow] = a1.y;
        As[koff + 6][lrow] = a1.z; As[koff + 7][lrow] = a1.w;
        Bs[koff + 0][lrow] = b0.x; Bs[koff + 1][lrow] = b0.y;
        Bs[koff + 2][lrow] = b0.z; Bs[koff + 3][lrow] = b0.w;
        Bs[koff + 4][lrow] = b1.x; Bs[koff + 5][lrow] = b1.y;
        Bs[koff + 6][lrow] = b1.z; Bs[koff + 7][lrow] = b1.w;
        __syncthreads();

        #pragma unroll
        for (int kk = 0; kk < 16; kk++) {
            ull rap[4];
            *(float4*)(&rap[0]) = *(const float4*)&As[kk][tr];
            *(float4*)(&rap[2]) = *(const float4*)&As[kk][tr + 4];
            {
                float4 rb = *(const float4*)&Bs[kk][tc];
                ull bd0 = dupf(rb.x), bd1 = dupf(rb.y);
                ull bd2 = dupf(rb.z), bd3 = dupf(rb.w);
                #pragma unroll
                for (int p = 0; p < 4; p++) {
                    FFMA2(accp[p][0], rap[p], bd0);
                    FFMA2(accp[p][1], rap[p], bd1);
                    FFMA2(accp[p][2], rap[p], bd2);
                    FFMA2(accp[p][3], rap[p], bd3);
                }
            }
            {
                float4 rb = *(const float4*)&Bs[kk][64 + tc];
                ull bd0 = dupf(rb.x), bd1 = dupf(rb.y);
                ull bd2 = dupf(rb.z), bd3 = dupf(rb.w);
                #pragma unroll
                for (int p = 0; p < 4; p++) {
                    FFMA2(accp[p][4], rap[p], bd0);
                    FFMA2(accp[p][5], rap[p], bd1);
                    FFMA2(accp[p][6], rap[p], bd2);
                    FFMA2(accp[p][7], rap[p], bd3);
                }
            }
        }
    }

    #pragma unroll
    for (int p = 0; p < 4; p++) {
        long r0r = row0 + tr + 2 * p;
        float o0a[4], o1a[4], o0b[4], o1b[4];
        #pragma unroll
        for (int j = 0; j < 4; j++) {
            o0a[j] = lo32(accp[p][j]);
            o1a[j] = hi32(accp[p][j]);
            o0b[j] = lo32(accp[p][4 + j]);
            o1b[j] = hi32(accp[p][4 + j]);
        }
        *(float4*)(Cz + r0r * N + col0 + tc)            = *(float4*)(o0a);
        *(float4*)(Cz + r0r * N + col0 + 64 + tc)       = *(float4*)(o0b);
        *(float4*)(Cz + (r0r + 1) * N + col0 + tc)      = *(float4*)(o1a);
        *(float4*)(Cz + (r0r + 1) * N + col0 + 64 + tc) = *(float4*)(o1b);
    }
}

// ---------------------------------------------------------------------------
// Small fp32 NT GEMM (64x64, 4x4, FFMA2) with A-combine mode.
// ---------------------------------------------------------------------------
__global__ void gemm_nt_64(const float* __restrict__ A,
                           int nslabs, size_t slabStride,
                           const float* __restrict__ ab,
                           const float* __restrict__ B,
                           const float* __restrict__ bias,
                           float* __restrict__ C,
                           int M, int N, int K)
{
    __shared__ float As[16][64];
    __shared__ float Bs[16][64];
    int tid = threadIdx.x;
    int row0 = blockIdx.y * 64;
    int col0 = blockIdx.x * 64;

    int lr = tid >> 2;
    int lk = (tid & 3) << 2;
    int tr = tid >> 4;
    int tc = tid & 15;
    ull accp[2][4] = {};
    const float* Ap = A + (long)(row0 + lr) * K + lk;
    const float* Bp = B + (long)(col0 + lr) * K + lk;
    for (int k0 = 0; k0 < K; k0 += 16) {
        float4 a = *(const float4*)(Ap + k0);
        if (nslabs > 1) {
            #pragma unroll 3
            for (int z = 1; z < nslabs; z++) {
                float4 a2 = *(const float4*)(Ap + z * slabStride + k0);
                a.x += a2.x; a.y += a2.y; a.z += a2.z; a.w += a2.w;
            }
            float4 av = *(const float4*)(ab + lk + k0);
            a.x = fmaxf(a.x + av.x, 0.f);
            a.y = fmaxf(a.y + av.y, 0.f);
            a.z = fmaxf(a.z + av.z, 0.f);
            a.w = fmaxf(a.w + av.w, 0.f);
        }
        float4 bq = *(const float4*)(Bp + k0);
        As[lk + 0][lr] = a.x;  As[lk + 1][lr] = a.y;
        As[lk + 2][lr] = a.z;  As[lk + 3][lr] = a.w;
        Bs[lk + 0][lr] = bq.x; Bs[lk + 1][lr] = bq.y;
        Bs[lk + 2][lr] = bq.z; Bs[lk + 3][lr] = bq.w;
        __syncthreads();
        #pragma unroll
        for (int kk = 0; kk < 16; kk++) {
            ull rap[2];
            *(float4*)(&rap[0]) = *(const float4*)&As[kk][tr * 4];
            float4 rbv = *(const float4*)&Bs[kk][tc * 4];
            ull bd0 = dupf(rbv.x);
            ull bd1 = dupf(rbv.y);
            ull bd2 = dupf(rbv.z);
            ull bd3 = dupf(rbv.w);
            #pragma unroll
            for (int p = 0; p < 2; p++) {
                FFMA2(accp[p][0], rap[p], bd0);
                FFMA2(accp[p][1], rap[p], bd1);
                FFMA2(accp[p][2], rap[p], bd2);
                FFMA2(accp[p][3], rap[p], bd3);
            }
        }
        __syncthreads();
    }
    #pragma unroll
    for (int p = 0; p < 2; p++) {
        long r0r = row0 + tr * 4 + 2 * p;
        #pragma unroll
        for (int j = 0; j < 4; j++) {
            int c = col0 + tc * 4 + j;
            float v0 = lo32(accp[p][j]);
            float v1 = hi32(accp[p][j]);
            if (bias) { v0 += bias[c]; v1 += bias[c]; }
            C[r0r * N + c]       = v0;
            C[(r0r + 1) * N + c] = v1;
        }
    }
}

// ---------------------------------------------------------------------------
// Flash attention: 1 warp per batch, zero smem, single pass over k0.
// Sums 2 qk slabs in q-load. launch_bounds(128,5) forces regs<=102 for
// 5 CTAs/SM occupancy (live state ~90 regs; no spill expected).
// ---------------------------------------------------------------------------
__global__ void __launch_bounds__(128, 5)
attn_flash_kernel(const float* __restrict__ seq,
                  const float* __restrict__ seq_e,
                  const float* __restrict__ seq_t,
                  const int* __restrict__ mask,
                  const float* __restrict__ qk,
                  float* __restrict__ ctx,
                  float* __restrict__ attn_out)
{
    const int lane = threadIdx.x & 31;
    const long b = (long)blockIdx.x * 4 + (threadIdx.x >> 5);

    ull q0p[6], q1p[6];
    {
        const float* qp  = qk + b * 768 + lane * 4;
        const float* qp2 = qp + (size_t)Bsz * 768;
        #pragma unroll
        for (int it = 0; it < 3; it++) {
            float4 u = *(const float4*)(qp + it * 128);
            float4 v = *(const float4*)(qp2 + it * 128);
            float4 s = make_float4(u.x + v.x, u.y + v.y, u.z + v.z, u.w + v.w);
            *(float4*)(&q0p[it * 2]) = s;
            u = *(const float4*)(qp + 384 + it * 128);
            v = *(const float4*)(qp2 + 384 + it * 128);
            s = make_float4(u.x + v.x, u.y + v.y, u.z + v.z, u.w + v.w);
            *(float4*)(&q1p[it * 2]) = s;
        }
    }

    ull c0p[6] = {}, c1p[6] = {};
    float m0 = -1e30f, m1 = -1e30f, l0 = 0.f, l1 = 0.f;
    float lg0[2], lg1[2];

    const float* p0 = seq   + b * 64 * 128 + lane * 4;
    const float* p1 = seq_e + b * 64 * 128 + lane * 4;
    const float* p2 = seq_t + b * 64 * 128 + lane * 4;
    const int*   mp = mask + b * 64;

    const float SCALE = 0.07216878364870323f;   // 1/sqrt(192)

    #pragma unroll 4
    for (int n = 0; n < 64; n++) {
        ull kp[6];
        *(float4*)(&kp[0]) = *(const float4*)(p0 + n * 128);
        *(float4*)(&kp[2]) = *(const float4*)(p1 + n * 128);
        *(float4*)(&kp[4]) = *(const float4*)(p2 + n * 128);
        int mk = mp[n];

        ull s0p = 0, s1p = 0;
        #pragma unroll
        for (int j = 0; j < 6; j++) {
            FFMA2(s0p, kp[j], q0p[j]);
            FFMA2(s1p, kp[j], q1p[j]);
        }
        float s0 = lo32(s0p) + hi32(s0p);
        float s1 = lo32(s1p) + hi32(s1p);

        #pragma unroll
        for (int o = 16; o; o >>= 1) {
            s0 += __shfl_xor_sync(0xffffffffu, s0, o);
            s1 += __shfl_xor_sync(0xffffffffu, s1, o);
        }
        s0 *= SCALE;
        s1 *= SCALE;
        if (mk != 0) { s0 = -1e10f; s1 = -1e10f; }

        if ((n & 31) == lane) {
            lg0[n >> 5] = s0;
            lg1[n >> 5] = s1;
        }

        float nm0 = fmaxf(m0, s0);
        float r0  = __expf(m0 - nm0);
        float e0  = __expf(s0 - nm0);
        m0 = nm0;
        l0 = fmaf(l0, r0, e0);
        {
            ull rd = dupf(r0), ed = dupf(e0);
            #pragma unroll
            for (int j = 0; j < 6; j++) {
                MUL2(c0p[j], c0p[j], rd);
                FFMA2(c0p[j], ed, kp[j]);
            }
        }
        float nm1 = fmaxf(m1, s1);
        float r1  = __expf(m1 - nm1);
        float e1  = __expf(s1 - nm1);
        m1 = nm1;
        l1 = fmaf(l1, r1, e1);
        {
            ull rd = dupf(r1), ed = dupf(e1);
            #pragma unroll
            for (int j = 0; j < 6; j++) {
                MUL2(c1p[j], c1p[j], rd);
                FFMA2(c1p[j], ed, kp[j]);
            }
        }
    }

    const float inv0 = 1.f / l0;
    const float inv1 = 1.f / l1;

    {
        float* cp = ctx + b * 768 + lane * 4;
        #pragma unroll
        for (int it = 0; it < 3; it++) {
            float o0[4], o1[4];
            o0[0] = lo32(c0p[it*2])   * inv0; o0[1] = hi32(c0p[it*2])   * inv0;
            o0[2] = lo32(c0p[it*2+1]) * inv0; o0[3] = hi32(c0p[it*2+1]) * inv0;
            o1[0] = lo32(c1p[it*2])   * inv1; o1[1] = hi32(c1p[it*2])   * inv1;
            o1[2] = lo32(c1p[it*2+1]) * inv1; o1[3] = hi32(c1p[it*2+1]) * inv1;
            *(float4*)(cp + it * 128)       = *(float4*)(o0);
            *(float4*)(cp + 384 + it * 128) = *(float4*)(o1);
        }
    }

    attn_out[b * 64 + lane]                     = __expf(lg0[0] - m0) * inv0;
    attn_out[b * 64 + 32 + lane]                = __expf(lg0[1] - m0) * inv0;
    attn_out[((long)Bsz + b) * 64 + lane]       = __expf(lg1[0] - m1) * inv1;
    attn_out[((long)Bsz + b) * 64 + 32 + lane]  = __expf(lg1[1] - m1) * inv1;
}

// ---------------------------------------------------------------------------
// res = 3 out-slabs + bo + q0 ; LayerNorm(384) ; x = [ln_out | src]
// ---------------------------------------------------------------------------
__global__ void ln_kernel(const float* __restrict__ outp,
                          const float* __restrict__ bo,
                          const float* __restrict__ src,
                          const float* __restrict__ src_t,
                          const float* __restrict__ g,
                          const float* __restrict__ bta,
                          float* __restrict__ x)
{
    const size_t SLAB = (size_t)Bsz * 384;
    int wid = threadIdx.x >> 5, lane = threadIdx.x & 31;
    long b = (long)blockIdx.x * 8 + wid;
    float r[12];
    float sum = 0.f, sq = 0.f;
    #pragma unroll
    for (int i = 0; i < 12; i++) {
        int m = lane + i * 32;
        size_t idx = b * 384 + m;
        float v = outp[idx] + outp[idx + SLAB] + outp[idx + 2 * SLAB] + bo[m];
        if (i < 4)       v += src[b * 128 + m];
        else if (i >= 8) v += src_t[b * 128 + (m - 256)];
        r[i] = v;
        sum += v;
        sq  = fmaf(v, v, sq);
    }
    #pragma unroll
    for (int o = 16; o; o >>= 1) {
        sum += __shfl_xor_sync(0xffffffffu, sum, o);
        sq  += __shfl_xor_sync(0xffffffffu, sq, o);
    }
    float mu  = sum * (1.f / 384.f);
    float var = sq * (1.f / 384.f) - mu * mu;
    float inv = rsqrtf(var + 1e-5f);
    #pragma unroll
    for (int i = 0; i < 12; i++) {
        int m = lane + i * 32;
        x[b * 512 + m] = (r[i] - mu) * inv * g[m] + bta[m];
    }
    #pragma unroll
    for (int i = 0; i < 4; i++) {
        int m = lane + i * 32;
        x[b * 512 + 384 + m] = src[b * 128 + m];
    }
}

// ---------------------------------------------------------------------------

extern "C" void kernel_launch(void* const* d_in, const int* in_sizes, int n_in,
                              void* d_out, int out_size)
{
    const float* src   = (const float*)d_in[0];
    const float* src_t = (const float*)d_in[1];
    const float* seq   = (const float*)d_in[2];
    const float* seq_t = (const float*)d_in[3];
    const float* seq_e = (const float*)d_in[4];
    const int*   mask  = (const int*)d_in[5];
    const float* Wq   = (const float*)d_in[6];
    const float* Wk   = (const float*)d_in[7];
    const float* Wv   = (const float*)d_in[8];
    const float* Wo   = (const float*)d_in[9];
    const float* bo   = (const float*)d_in[10];
    const float* ln_g = (const float*)d_in[11];
    const float* ln_b = (const float*)d_in[12];
    const float* W1   = (const float*)d_in[13];
    const float* b1   = (const float*)d_in[14];
    const float* W2   = (const float*)d_in[15];
    const float* b2   = (const float*)d_in[16];

    float* y        = (float*)d_out;
    float* attn_out = (float*)d_out + Bsz * 128;

    float *p_wqk, *p_wov, *p_qk, *p_ctx, *p_out, *p_x, *p_h;
    cudaGetSymbolAddress((void**)&p_wqk, g_wqk);
    cudaGetSymbolAddress((void**)&p_wov, g_wov);
    cudaGetSymbolAddress((void**)&p_qk,  g_qk);
    cudaGetSymbolAddress((void**)&p_ctx, g_ctx);
    cudaGetSymbolAddress((void**)&p_out, g_out);
    cudaGetSymbolAddress((void**)&p_x,   g_x);
    cudaGetSymbolAddress((void**)&p_h,   g_h);

    // 1. fold Wqk (needed by gemm1)
    fold_qk_kernel<<<768, dim3(16, 16)>>>(Wk, Wq, p_wqk);

    // 2. qk slabs = [src|src_t] @ Wqk^T   (K=256, split-K=2 -> 384 CTAs)
    gemm_nt_128x128<<<dim3(768 / 128, Bsz / 128, 2), 256>>>(
        src, src_t, p_wqk, p_qk, Bsz, 768, 256);

    // 3. fold Wov (needed only by gemm2; keeps attn in profiled slot 4)
    fold_ov_kernel<<<1152, dim3(16, 16)>>>(Wo, Wv, p_wov);

    // 4. flash attention [profiled slot] (sums 2 qk slabs)
    attn_flash_kernel<<<Bsz / 4, 128>>>(seq, seq_e, seq_t, mask, p_qk, p_ctx, attn_out);

    // 5. out slabs = ctx @ Wov^T   (K=768, split-K=3 -> 288 CTAs)
    gemm_nt_128x128<<<dim3(384 / 128, Bsz / 128, 3), 256>>>(
        p_ctx, nullptr, p_wov, p_out, Bsz, 384, 768);

    // 6. residual (3 slabs + bo) + LN + concat
    ln_kernel<<<Bsz / 8, 256>>>(p_out, bo, src, src_t, ln_g, ln_b, p_x);

    // 7. FFN1: h slabs = x @ W1^T (K=512, split-K=4 -> 256 CTAs)
    gemm_nt_128x64<<<dim3(128 / 64, Bsz / 128, 4), 256>>>(
        p_x, nullptr, W1, p_h, Bsz, 128, 512);

    // 8. FFN2: y = relu(sum_z h_z + b1) @ W2^T + b2   (4-slab A-combine)
    gemm_nt_64<<<dim3(2, Bsz / 64), 256>>>(p_h, 4, (size_t)Bsz * 128, b1,
                                           W2, b2, y, Bsz, 128, 128);
}

// round 16
// speedup vs baseline: 1.1681x; 1.1681x over previous
#include <cuda_runtime.h>
#include <cuda_bf16.h>

// ---------------------------------------------------------------------------
// TGAT restructured (math unchanged). Composition of verified-best pieces:
//   fold_both(1) -> gemm1(2) -> attn(3) -> gemm2(4, profiled) -> LN(5) ->
//   ffn1(6) -> ffn2(7)
//   gemm1: 128x128-cf FFMA2 single-buffer, concat A-load, split-K=2 (384 CTAs)
//   attn : flash, 1 warp/batch, packed f32x2, natural regs (NO launch_bounds
//          cap — R15 showed the cap spills); sums 2 qk slabs in q-load
//   gemm2: 128x128-cf FFMA2 single-buffer, split-K=3 (288 CTAs)
//   LN   : sums 3 slabs + bo
//   ffn1 : 128x64 FFMA2 split-K=4 ; ffn2: 64x64 FFMA2, 4-slab A-combine
// ---------------------------------------------------------------------------

#define Bsz 4096
typedef unsigned long long ull;

__device__ __align__(16) float g_wqk[768 * 256];
__device__ __align__(16) float g_wov[384 * 768];
__device__ __align__(16) float g_qk [2 * Bsz * 768];   // 2 split-K slabs
__device__ __align__(16) float g_ctx[Bsz * 768];
__device__ __align__(16) float g_out[3 * Bsz * 384];   // split-K=3 slabs
__device__ __align__(16) float g_x  [Bsz * 512];
__device__ __align__(16) float g_h  [4 * Bsz * 128];   // split-K=4 slabs

#define FFMA2(d, a, b) \
    asm("fma.rn.f32x2 %0, %1, %2, %0;" : "+l"(d) : "l"(a), "l"(b))
#define MUL2(d, a, b) \
    asm("mul.rn.f32x2 %0, %1, %2;" : "=l"(d) : "l"(a), "l"(b))
__device__ __forceinline__ ull dupf(float x) {
    ull d;
    unsigned r = __float_as_uint(x);
    asm("mov.b64 %0, {%1, %1};" : "=l"(d) : "r"(r));
    return d;
}
__device__ __forceinline__ float lo32(ull v) { return __uint_as_float((unsigned)v); }
__device__ __forceinline__ float hi32(ull v) { return __uint_as_float((unsigned)(v >> 32)); }

// ---------------------------------------------------------------------------
// Combined folds (one launch)
// ---------------------------------------------------------------------------
__global__ void fold_both_kernel(const float* __restrict__ Wk,
                                 const float* __restrict__ Wq,
                                 const float* __restrict__ Wo,
                                 const float* __restrict__ Wv,
                                 float* __restrict__ Wqk,
                                 float* __restrict__ Wov)
{
    __shared__ float sA[16][16];
    __shared__ float sB[16][16];
    int tx = threadIdx.x, ty = threadIdx.y;
    int bid = blockIdx.x;
    if (bid < 768) {
        int c0 = (bid & 15) * 16;
        int r0 = (bid >> 4) * 16;
        int h    = r0 / 384;
        int mloc = r0 % 384;
        int c = c0 + tx;
        int mprime = (c < 128) ? c : c + 128;
        float acc = 0.f;
        for (int dt = 0; dt < 192; dt += 16) {
            int d = h * 192 + dt + ty;
            sA[ty][tx] = Wk[d * 384 + (mloc + tx)];
            sB[ty][tx] = Wq[d * 384 + mprime];
            __syncthreads();
            #pragma unroll
            for (int kk = 0; kk < 16; kk++)
                acc = fmaf(sA[kk][ty], sB[kk][tx], acc);
            __syncthreads();
        }
        Wqk[(r0 + ty) * 256 + c0 + tx] = acc;
    } else {
        int b2 = bid - 768;
        int c0 = (b2 % 48) * 16;
        int r0 = (b2 / 48) * 16;
        int h  = c0 / 384;
        int m0 = c0 % 384;
        float acc = 0.f;
        for (int dt = 0; dt < 192; dt += 16) {
            sA[ty][tx] = Wo[(r0 + ty) * 384 + (h * 192 + dt + tx)];
            sB[ty][tx] = Wv[(h * 192 + dt + ty) * 384 + (m0 + tx)];
            __syncthreads();
            #pragma unroll
            for (int kk = 0; kk < 16; kk++)
                acc = fmaf(sA[ty][kk], sB[kk][tx], acc);
            __syncthreads();
        }
        Wov[(r0 + ty) * 768 + c0 + tx] = acc;
    }
}

// ---------------------------------------------------------------------------
// fp32 NT GEMM: 128x64 tile, BK=16, 256 threads, 8x4 micro, FFMA2,
// double-buffered. Concat mode via A1. Split-K via gridDim.z. (FFN1.)
// ---------------------------------------------------------------------------
__global__ void gemm_nt_128x64(const float* __restrict__ A0,
                               const float* __restrict__ A1,
                               const float* __restrict__ B,
                               float* __restrict__ C,
                               int M, int N, int K)
{
    __shared__ float As[2][16][128];
    __shared__ float Bs[2][16][64];
    const int tid  = threadIdx.x;
    const int row0 = blockIdx.y * 128;
    const int col0 = blockIdx.x * 64;
    const int Kslice = K / gridDim.z;
    const int kbase  = blockIdx.z * Kslice;
    float* Cz = C + (size_t)blockIdx.z * (size_t)M * N;

    const int arow  = tid >> 1;
    const int akoff = (tid & 1) << 3;
    const int brow  = tid >> 2;
    const int bkoff = (tid & 3) << 2;
    const float* Bp = B + (long)(col0 + brow) * K + kbase + bkoff;

    const int tr = (tid >> 4) << 3;
    const int tc = (tid & 15) << 2;

    ull accp[4][4] = {};

    float4 a0, a1, b0;

    auto loadA = [&](int k) {
        int kk = kbase + k + akoff;
        long row = row0 + arow;
        const float* p;
        if (A1) p = (kk < 128) ? (A0 + row * 128 + kk)
                               : (A1 + row * 128 + (kk - 128));
        else    p = A0 + row * (long)K + kk;
        a0 = *(const float4*)p;
        a1 = *(const float4*)(p + 4);
    };
    auto loadB = [&](int k) { b0 = *(const float4*)(Bp + k); };
    auto stAB = [&](int buf) {
        As[buf][akoff + 0][arow] = a0.x; As[buf][akoff + 1][arow] = a0.y;
        As[buf][akoff + 2][arow] = a0.z; As[buf][akoff + 3][arow] = a0.w;
        As[buf][akoff + 4][arow] = a1.x; As[buf][akoff + 5][arow] = a1.y;
        As[buf][akoff + 6][arow] = a1.z; As[buf][akoff + 7][arow] = a1.w;
        Bs[buf][bkoff + 0][brow] = b0.x; Bs[buf][bkoff + 1][brow] = b0.y;
        Bs[buf][bkoff + 2][brow] = b0.z; Bs[buf][bkoff + 3][brow] = b0.w;
    };

    loadA(0); loadB(0);
    stAB(0);
    __syncthreads();

    int buf = 0;
    for (int k0 = 0; k0 < Kslice; k0 += 16) {
        const bool nxt = (k0 + 16) < Kslice;
        if (nxt) { loadA(k0 + 16); loadB(k0 + 16); }
        #pragma unroll
        for (int kk = 0; kk < 16; kk++) {
            ull rap[4];
            *(float4*)(&rap[0]) = *(const float4*)&As[buf][kk][tr];
            *(float4*)(&rap[2]) = *(const float4*)&As[buf][kk][tr + 4];
            float4 rbv = *(const float4*)&Bs[buf][kk][tc];
            ull bd0 = dupf(rbv.x), bd1 = dupf(rbv.y);
            ull bd2 = dupf(rbv.z), bd3 = dupf(rbv.w);
            #pragma unroll
            for (int p = 0; p < 4; p++) {
                FFMA2(accp[p][0], rap[p], bd0);
                FFMA2(accp[p][1], rap[p], bd1);
                FFMA2(accp[p][2], rap[p], bd2);
                FFMA2(accp[p][3], rap[p], bd3);
            }
        }
        if (nxt) {
            buf ^= 1;
            stAB(buf);
            __syncthreads();
        }
    }

    #pragma unroll
    for (int p = 0; p < 4; p++) {
        long r0r = row0 + tr + 2 * p;
        float o0[4], o1[4];
        #pragma unroll
        for (int j = 0; j < 4; j++) {
            o0[j] = lo32(accp[p][j]);
            o1[j] = hi32(accp[p][j]);
        }
        *(float4*)(Cz + r0r * N + col0 + tc)       = *(float4*)(o0);
        *(float4*)(Cz + (r0r + 1) * N + col0 + tc) = *(float4*)(o1);
    }
}

// ---------------------------------------------------------------------------
// fp32 NT GEMM: 128x128 tile, BK=16, 256 threads, 8x8 micro, FFMA2,
// single-buffered, occ-2, conflict-free B reads (16B lane stride).
// Concat mode via A1. Split-K via gridDim.z.
// ---------------------------------------------------------------------------
__global__ void __launch_bounds__(256, 2)
gemm_nt_128x128(const float* __restrict__ A0, const float* __restrict__ A1,
                const float* __restrict__ B, float* __restrict__ C,
                int M, int N, int K)
{
    __shared__ float As[16][128];
    __shared__ float Bs[16][128];
    const int tid  = threadIdx.x;
    const int row0 = blockIdx.y * 128;
    const int col0 = blockIdx.x * 128;
    const int Kslice = K / gridDim.z;
    const int kbase  = blockIdx.z * Kslice;
    float* Cz = C + (size_t)blockIdx.z * (size_t)M * N;

    const int lrow = tid >> 1;
    const int koff = (tid & 1) << 3;
    const int tr = (tid >> 4) << 3;
    const int tc = (tid & 15) << 2;      // 16B stride: conflict-free

    ull accp[4][8] = {};   // j 0-3: cols tc+j ; j 4-7: cols 64+tc+(j-4)

    const float* Bp = B + (long)(col0 + lrow) * K + kbase + koff;
    const long arowg = row0 + lrow;

    for (int k0 = 0; k0 < Kslice; k0 += 16) {
        float4 a0, a1, b0, b1;
        {
            int kk = kbase + k0 + koff;
            const float* p;
            if (A1) p = (kk < 128) ? (A0 + arowg * 128 + kk)
                                   : (A1 + arowg * 128 + (kk - 128));
            else    p = A0 + arowg * (long)K + kk;
            a0 = *(const float4*)p;
            a1 = *(const float4*)(p + 4);
            b0 = *(const float4*)(Bp + k0);
            b1 = *(const float4*)(Bp + k0 + 4);
        }
        __syncthreads();
        As[koff + 0][lrow] = a0.x; As[koff + 1][lrow] = a0.y;
        As[koff + 2][lrow] = a0.z; As[koff + 3][lrow] = a0.w;
        As[koff + 4][lrow] = a1.x; As[koff + 5][lrow] = a1.y;
        As[koff + 6][lrow] = a1.z; As[koff + 7][lrow] = a1.w;
        Bs[koff + 0][lrow] = b0.x; Bs[koff + 1][lrow] = b0.y;
        Bs[koff + 2][lrow] = b0.z; Bs[koff + 3][lrow] = b0.w;
        Bs[koff + 4][lrow] = b1.x; Bs[koff + 5][lrow] = b1.y;
        Bs[koff + 6][lrow] = b1.z; Bs[koff + 7][lrow] = b1.w;
        __syncthreads();

        #pragma unroll
        for (int kk = 0; kk < 16; kk++) {
            ull rap[4];
            *(float4*)(&rap[0]) = *(const float4*)&As[kk][tr];
            *(float4*)(&rap[2]) = *(const float4*)&As[kk][tr + 4];
            {
                float4 rb = *(const float4*)&Bs[kk][tc];
                ull bd0 = dupf(rb.x), bd1 = dupf(rb.y);
                ull bd2 = dupf(rb.z), bd3 = dupf(rb.w);
                #pragma unroll
                for (int p = 0; p < 4; p++) {
                    FFMA2(accp[p][0], rap[p], bd0);
                    FFMA2(accp[p][1], rap[p], bd1);
                    FFMA2(accp[p][2], rap[p], bd2);
                    FFMA2(accp[p][3], rap[p], bd3);
                }
            }
            {
                float4 rb = *(const float4*)&Bs[kk][64 + tc];
                ull bd0 = dupf(rb.x), bd1 = dupf(rb.y);
                ull bd2 = dupf(rb.z), bd3 = dupf(rb.w);
                #pragma unroll
                for (int p = 0; p < 4; p++) {
                    FFMA2(accp[p][4], rap[p], bd0);
                    FFMA2(accp[p][5], rap[p], bd1);
                    FFMA2(accp[p][6], rap[p], bd2);
                    FFMA2(accp[p][7], rap[p], bd3);
                }
            }
        }
    }

    #pragma unroll
    for (int p = 0; p < 4; p++) {
        long r0r = row0 + tr + 2 * p;
        float o0a[4], o1a[4], o0b[4], o1b[4];
        #pragma unroll
        for (int j = 0; j < 4; j++) {
            o0a[j] = lo32(accp[p][j]);
            o1a[j] = hi32(accp[p][j]);
            o0b[j] = lo32(accp[p][4 + j]);
            o1b[j] = hi32(accp[p][4 + j]);
        }
        *(float4*)(Cz + r0r * N + col0 + tc)            = *(float4*)(o0a);
        *(float4*)(Cz + r0r * N + col0 + 64 + tc)       = *(float4*)(o0b);
        *(float4*)(Cz + (r0r + 1) * N + col0 + tc)      = *(float4*)(o1a);
        *(float4*)(Cz + (r0r + 1) * N + col0 + 64 + tc) = *(float4*)(o1b);
    }
}

// ---------------------------------------------------------------------------
// Small fp32 NT GEMM (64x64, 4x4, FFMA2) with A-combine mode.
// ---------------------------------------------------------------------------
__global__ void gemm_nt_64(const float* __restrict__ A,
                           int nslabs, size_t slabStride,
                           const float* __restrict__ ab,
                           const float* __restrict__ B,
                           const float* __restrict__ bias,
                           float* __restrict__ C,
                           int M, int N, int K)
{
    __shared__ float As[16][64];
    __shared__ float Bs[16][64];
    int tid = threadIdx.x;
    int row0 = blockIdx.y * 64;
    int col0 = blockIdx.x * 64;

    int lr = tid >> 2;
    int lk = (tid & 3) << 2;
    int tr = tid >> 4;
    int tc = tid & 15;
    ull accp[2][4] = {};
    const float* Ap = A + (long)(row0 + lr) * K + lk;
    const float* Bp = B + (long)(col0 + lr) * K + lk;
    for (int k0 = 0; k0 < K; k0 += 16) {
        float4 a = *(const float4*)(Ap + k0);
        if (nslabs > 1) {
            #pragma unroll 3
            for (int z = 1; z < nslabs; z++) {
                float4 a2 = *(const float4*)(Ap + z * slabStride + k0);
                a.x += a2.x; a.y += a2.y; a.z += a2.z; a.w += a2.w;
            }
            float4 av = *(const float4*)(ab + lk + k0);
            a.x = fmaxf(a.x + av.x, 0.f);
            a.y = fmaxf(a.y + av.y, 0.f);
            a.z = fmaxf(a.z + av.z, 0.f);
            a.w = fmaxf(a.w + av.w, 0.f);
        }
        float4 bq = *(const float4*)(Bp + k0);
        As[lk + 0][lr] = a.x;  As[lk + 1][lr] = a.y;
        As[lk + 2][lr] = a.z;  As[lk + 3][lr] = a.w;
        Bs[lk + 0][lr] = bq.x; Bs[lk + 1][lr] = bq.y;
        Bs[lk + 2][lr] = bq.z; Bs[lk + 3][lr] = bq.w;
        __syncthreads();
        #pragma unroll
        for (int kk = 0; kk < 16; kk++) {
            ull rap[2];
            *(float4*)(&rap[0]) = *(const float4*)&As[kk][tr * 4];
            float4 rbv = *(const float4*)&Bs[kk][tc * 4];
            ull bd0 = dupf(rbv.x);
            ull bd1 = dupf(rbv.y);
            ull bd2 = dupf(rbv.z);
            ull bd3 = dupf(rbv.w);
            #pragma unroll
            for (int p = 0; p < 2; p++) {
                FFMA2(accp[p][0], rap[p], bd0);
                FFMA2(accp[p][1], rap[p], bd1);
                FFMA2(accp[p][2], rap[p], bd2);
                FFMA2(accp[p][3], rap[p], bd3);
            }
        }
        __syncthreads();
    }
    #pragma unroll
    for (int p = 0; p < 2; p++) {
        long r0r = row0 + tr * 4 + 2 * p;
        #pragma unroll
        for (int j = 0; j < 4; j++) {
            int c = col0 + tc * 4 + j;
            float v0 = lo32(accp[p][j]);
            float v1 = hi32(accp[p][j]);
            if (bias) { v0 += bias[c]; v1 += bias[c]; }
            C[r0r * N + c]       = v0;
            C[(r0r + 1) * N + c] = v1;
        }
    }
}

// ---------------------------------------------------------------------------
// Flash attention: 1 warp per batch, zero smem, single pass over k0.
// Sums 2 qk slabs in q-load. Natural register allocation (no cap).
// ---------------------------------------------------------------------------
__global__ void __launch_bounds__(128)
attn_flash_kernel(const float* __restrict__ seq,
                  const float* __restrict__ seq_e,
                  const float* __restrict__ seq_t,
                  const int* __restrict__ mask,
                  const float* __restrict__ qk,
                  float* __restrict__ ctx,
                  float* __restrict__ attn_out)
{
    const int lane = threadIdx.x & 31;
    const long b = (long)blockIdx.x * 4 + (threadIdx.x >> 5);

    ull q0p[6], q1p[6];
    {
        const float* qp  = qk + b * 768 + lane * 4;
        const float* qp2 = qp + (size_t)Bsz * 768;
        #pragma unroll
        for (int it = 0; it < 3; it++) {
            float4 u = *(const float4*)(qp + it * 128);
            float4 v = *(const float4*)(qp2 + it * 128);
            float4 s = make_float4(u.x + v.x, u.y + v.y, u.z + v.z, u.w + v.w);
            *(float4*)(&q0p[it * 2]) = s;
            u = *(const float4*)(qp + 384 + it * 128);
            v = *(const float4*)(qp2 + 384 + it * 128);
            s = make_float4(u.x + v.x, u.y + v.y, u.z + v.z, u.w + v.w);
            *(float4*)(&q1p[it * 2]) = s;
        }
    }

    ull c0p[6] = {}, c1p[6] = {};
    float m0 = -1e30f, m1 = -1e30f, l0 = 0.f, l1 = 0.f;
    float lg0[2], lg1[2];

    const float* p0 = seq   + b * 64 * 128 + lane * 4;
    const float* p1 = seq_e + b * 64 * 128 + lane * 4;
    const float* p2 = seq_t + b * 64 * 128 + lane * 4;
    const int*   mp = mask + b * 64;

    const float SCALE = 0.07216878364870323f;   // 1/sqrt(192)

    #pragma unroll 4
    for (int n = 0; n < 64; n++) {
        ull kp[6];
        *(float4*)(&kp[0]) = *(const float4*)(p0 + n * 128);
        *(float4*)(&kp[2]) = *(const float4*)(p1 + n * 128);
        *(float4*)(&kp[4]) = *(const float4*)(p2 + n * 128);
        int mk = mp[n];

        ull s0p = 0, s1p = 0;
        #pragma unroll
        for (int j = 0; j < 6; j++) {
            FFMA2(s0p, kp[j], q0p[j]);
            FFMA2(s1p, kp[j], q1p[j]);
        }
        float s0 = lo32(s0p) + hi32(s0p);
        float s1 = lo32(s1p) + hi32(s1p);

        #pragma unroll
        for (int o = 16; o; o >>= 1) {
            s0 += __shfl_xor_sync(0xffffffffu, s0, o);
            s1 += __shfl_xor_sync(0xffffffffu, s1, o);
        }
        s0 *= SCALE;
        s1 *= SCALE;
        if (mk != 0) { s0 = -1e10f; s1 = -1e10f; }

        if ((n & 31) == lane) {
            lg0[n >> 5] = s0;
            lg1[n >> 5] = s1;
        }

        float nm0 = fmaxf(m0, s0);
        float r0  = __expf(m0 - nm0);
        float e0  = __expf(s0 - nm0);
        m0 = nm0;
        l0 = fmaf(l0, r0, e0);
        {
            ull rd = dupf(r0), ed = dupf(e0);
            #pragma unroll
            for (int j = 0; j < 6; j++) {
                MUL2(c0p[j], c0p[j], rd);
                FFMA2(c0p[j], ed, kp[j]);
            }
        }
        float nm1 = fmaxf(m1, s1);
        float r1  = __expf(m1 - nm1);
        float e1  = __expf(s1 - nm1);
        m1 = nm1;
        l1 = fmaf(l1, r1, e1);
        {
            ull rd = dupf(r1), ed = dupf(e1);
            #pragma unroll
            for (int j = 0; j < 6; j++) {
                MUL2(c1p[j], c1p[j], rd);
                FFMA2(c1p[j], ed, kp[j]);
            }
        }
    }

    const float inv0 = 1.f / l0;
    const float inv1 = 1.f / l1;

    {
        float* cp = ctx + b * 768 + lane * 4;
        #pragma unroll
        for (int it = 0; it < 3; it++) {
            float o0[4], o1[4];
            o0[0] = lo32(c0p[it*2])   * inv0; o0[1] = hi32(c0p[it*2])   * inv0;
            o0[2] = lo32(c0p[it*2+1]) * inv0; o0[3] = hi32(c0p[it*2+1]) * inv0;
            o1[0] = lo32(c1p[it*2])   * inv1; o1[1] = hi32(c1p[it*2])   * inv1;
            o1[2] = lo32(c1p[it*2+1]) * inv1; o1[3] = hi32(c1p[it*2+1]) * inv1;
            *(float4*)(cp + it * 128)       = *(float4*)(o0);
            *(float4*)(cp + 384 + it * 128) = *(float4*)(o1);
        }
    }

    attn_out[b * 64 + lane]                     = __expf(lg0[0] - m0) * inv0;
    attn_out[b * 64 + 32 + lane]                = __expf(lg0[1] - m0) * inv0;
    attn_out[((long)Bsz + b) * 64 + lane]       = __expf(lg1[0] - m1) * inv1;
    attn_out[((long)Bsz + b) * 64 + 32 + lane]  = __expf(lg1[1] - m1) * inv1;
}

// ---------------------------------------------------------------------------
// res = 3 out-slabs + bo + q0 ; LayerNorm(384) ; x = [ln_out | src]
// ---------------------------------------------------------------------------
__global__ void ln_kernel(const float* __restrict__ outp,
                          const float* __restrict__ bo,
                          const float* __restrict__ src,
                          const float* __restrict__ src_t,
                          const float* __restrict__ g,
                          const float* __restrict__ bta,
                          float* __restrict__ x)
{
    const size_t SLAB = (size_t)Bsz * 384;
    int wid = threadIdx.x >> 5, lane = threadIdx.x & 31;
    long b = (long)blockIdx.x * 8 + wid;
    float r[12];
    float sum = 0.f, sq = 0.f;
    #pragma unroll
    for (int i = 0; i < 12; i++) {
        int m = lane + i * 32;
        size_t idx = b * 384 + m;
        float v = outp[idx] + outp[idx + SLAB] + outp[idx + 2 * SLAB] + bo[m];
        if (i < 4)       v += src[b * 128 + m];
        else if (i >= 8) v += src_t[b * 128 + (m - 256)];
        r[i] = v;
        sum += v;
        sq  = fmaf(v, v, sq);
    }
    #pragma unroll
    for (int o = 16; o; o >>= 1) {
        sum += __shfl_xor_sync(0xffffffffu, sum, o);
        sq  += __shfl_xor_sync(0xffffffffu, sq, o);
    }
    float mu  = sum * (1.f / 384.f);
    float var = sq * (1.f / 384.f) - mu * mu;
    float inv = rsqrtf(var + 1e-5f);
    #pragma unroll
    for (int i = 0; i < 12; i++) {
        int m = lane + i * 32;
        x[b * 512 + m] = (r[i] - mu) * inv * g[m] + bta[m];
    }
    #pragma unroll
    for (int i = 0; i < 4; i++) {
        int m = lane + i * 32;
        x[b * 512 + 384 + m] = src[b * 128 + m];
    }
}

// ---------------------------------------------------------------------------

extern "C" void kernel_launch(void* const* d_in, const int* in_sizes, int n_in,
                              void* d_out, int out_size)
{
    const float* src   = (const float*)d_in[0];
    const float* src_t = (const float*)d_in[1];
    const float* seq   = (const float*)d_in[2];
    const float* seq_t = (const float*)d_in[3];
    const float* seq_e = (const float*)d_in[4];
    const int*   mask  = (const int*)d_in[5];
    const float* Wq   = (const float*)d_in[6];
    const float* Wk   = (const float*)d_in[7];
    const float* Wv   = (const float*)d_in[8];
    const float* Wo   = (const float*)d_in[9];
    const float* bo   = (const float*)d_in[10];
    const float* ln_g = (const float*)d_in[11];
    const float* ln_b = (const float*)d_in[12];
    const float* W1   = (const float*)d_in[13];
    const float* b1   = (const float*)d_in[14];
    const float* W2   = (const float*)d_in[15];
    const float* b2   = (const float*)d_in[16];

    float* y        = (float*)d_out;
    float* attn_out = (float*)d_out + Bsz * 128;

    float *p_wqk, *p_wov, *p_qk, *p_ctx, *p_out, *p_x, *p_h;
    cudaGetSymbolAddress((void**)&p_wqk, g_wqk);
    cudaGetSymbolAddress((void**)&p_wov, g_wov);
    cudaGetSymbolAddress((void**)&p_qk,  g_qk);
    cudaGetSymbolAddress((void**)&p_ctx, g_ctx);
    cudaGetSymbolAddress((void**)&p_out, g_out);
    cudaGetSymbolAddress((void**)&p_x,   g_x);
    cudaGetSymbolAddress((void**)&p_h,   g_h);

    // 1. folds (merged, one launch)
    fold_both_kernel<<<1920, dim3(16, 16)>>>(Wk, Wq, Wo, Wv, p_wqk, p_wov);

    // 2. qk slabs = [src|src_t] @ Wqk^T   (K=256, split-K=2 -> 384 CTAs)
    gemm_nt_128x128<<<dim3(768 / 128, Bsz / 128, 2), 256>>>(
        src, src_t, p_wqk, p_qk, Bsz, 768, 256);

    // 3. flash attention (sums 2 qk slabs)
    attn_flash_kernel<<<Bsz / 4, 128>>>(seq, seq_e, seq_t, mask, p_qk, p_ctx, attn_out);

    // 4. out slabs = ctx @ Wov^T   (K=768, split-K=3 -> 288 CTAs) [profiled]
    gemm_nt_128x128<<<dim3(384 / 128, Bsz / 128, 3), 256>>>(
        p_ctx, nullptr, p_wov, p_out, Bsz, 384, 768);

    // 5. residual (3 slabs + bo) + LN + concat
    ln_kernel<<<Bsz / 8, 256>>>(p_out, bo, src, src_t, ln_g, ln_b, p_x);

    // 6. FFN1: h slabs = x @ W1^T (K=512, split-K=4 -> 256 CTAs)
    gemm_nt_128x64<<<dim3(128 / 64, Bsz / 128, 4), 256>>>(
        p_x, nullptr, W1, p_h, Bsz, 128, 512);

    // 7. FFN2: y = relu(sum_z h_z + b1) @ W2^T + b2   (4-slab A-combine)
    gemm_nt_64<<<dim3(2, Bsz / 64), 256>>>(p_h, 4, (size_t)Bsz * 128, b1,
                                           W2, b2, y, Bsz, 128, 128);
}

// round 17
// speedup vs baseline: 1.1755x; 1.0064x over previous
#include <cuda_runtime.h>
#include <cuda_bf16.h>

// ---------------------------------------------------------------------------
// TGAT restructured (math unchanged). R16 config + register-double-buffered
// prefetch in attention (software pipeline over tokens).
//   fold_both(1) -> gemm1(2) -> attn(3) -> gemm2(4, profiled anchor) ->
//   LN(5) -> ffn1(6) -> ffn2(7)
// ---------------------------------------------------------------------------

#define Bsz 4096
typedef unsigned long long ull;

__device__ __align__(16) float g_wqk[768 * 256];
__device__ __align__(16) float g_wov[384 * 768];
__device__ __align__(16) float g_qk [2 * Bsz * 768];   // 2 split-K slabs
__device__ __align__(16) float g_ctx[Bsz * 768];
__device__ __align__(16) float g_out[3 * Bsz * 384];   // split-K=3 slabs
__device__ __align__(16) float g_x  [Bsz * 512];
__device__ __align__(16) float g_h  [4 * Bsz * 128];   // split-K=4 slabs

#define FFMA2(d, a, b) \
    asm("fma.rn.f32x2 %0, %1, %2, %0;" : "+l"(d) : "l"(a), "l"(b))
#define MUL2(d, a, b) \
    asm("mul.rn.f32x2 %0, %1, %2;" : "=l"(d) : "l"(a), "l"(b))
__device__ __forceinline__ ull dupf(float x) {
    ull d;
    unsigned r = __float_as_uint(x);
    asm("mov.b64 %0, {%1, %1};" : "=l"(d) : "r"(r));
    return d;
}
__device__ __forceinline__ float lo32(ull v) { return __uint_as_float((unsigned)v); }
__device__ __forceinline__ float hi32(ull v) { return __uint_as_float((unsigned)(v >> 32)); }

// ---------------------------------------------------------------------------
// Combined folds (one launch)
// ---------------------------------------------------------------------------
__global__ void fold_both_kernel(const float* __restrict__ Wk,
                                 const float* __restrict__ Wq,
                                 const float* __restrict__ Wo,
                                 const float* __restrict__ Wv,
                                 float* __restrict__ Wqk,
                                 float* __restrict__ Wov)
{
    __shared__ float sA[16][16];
    __shared__ float sB[16][16];
    int tx = threadIdx.x, ty = threadIdx.y;
    int bid = blockIdx.x;
    if (bid < 768) {
        int c0 = (bid & 15) * 16;
        int r0 = (bid >> 4) * 16;
        int h    = r0 / 384;
        int mloc = r0 % 384;
        int c = c0 + tx;
        int mprime = (c < 128) ? c : c + 128;
        float acc = 0.f;
        for (int dt = 0; dt < 192; dt += 16) {
            int d = h * 192 + dt + ty;
            sA[ty][tx] = Wk[d * 384 + (mloc + tx)];
            sB[ty][tx] = Wq[d * 384 + mprime];
            __syncthreads();
            #pragma unroll
            for (int kk = 0; kk < 16; kk++)
                acc = fmaf(sA[kk][ty], sB[kk][tx], acc);
            __syncthreads();
        }
        Wqk[(r0 + ty) * 256 + c0 + tx] = acc;
    } else {
        int b2 = bid - 768;
        int c0 = (b2 % 48) * 16;
        int r0 = (b2 / 48) * 16;
        int h  = c0 / 384;
        int m0 = c0 % 384;
        float acc = 0.f;
        for (int dt = 0; dt < 192; dt += 16) {
            sA[ty][tx] = Wo[(r0 + ty) * 384 + (h * 192 + dt + tx)];
            sB[ty][tx] = Wv[(h * 192 + dt + ty) * 384 + (m0 + tx)];
            __syncthreads();
            #pragma unroll
            for (int kk = 0; kk < 16; kk++)
                acc = fmaf(sA[ty][kk], sB[kk][tx], acc);
            __syncthreads();
        }
        Wov[(r0 + ty) * 768 + c0 + tx] = acc;
    }
}

// ---------------------------------------------------------------------------
// fp32 NT GEMM: 128x64 tile, BK=16, 256 threads, 8x4 micro, FFMA2,
// double-buffered. Concat mode via A1. Split-K via gridDim.z. (FFN1.)
// ---------------------------------------------------------------------------
__global__ void gemm_nt_128x64(const float* __restrict__ A0,
                               const float* __restrict__ A1,
                               const float* __restrict__ B,
                               float* __restrict__ C,
                               int M, int N, int K)
{
    __shared__ float As[2][16][128];
    __shared__ float Bs[2][16][64];
    const int tid  = threadIdx.x;
    const int row0 = blockIdx.y * 128;
    const int col0 = blockIdx.x * 64;
    const int Kslice = K / gridDim.z;
    const int kbase  = blockIdx.z * Kslice;
    float* Cz = C + (size_t)blockIdx.z * (size_t)M * N;

    const int arow  = tid >> 1;
    const int akoff = (tid & 1) << 3;
    const int brow  = tid >> 2;
    const int bkoff = (tid & 3) << 2;
    const float* Bp = B + (long)(col0 + brow) * K + kbase + bkoff;

    const int tr = (tid >> 4) << 3;
    const int tc = (tid & 15) << 2;

    ull accp[4][4] = {};

    float4 a0, a1, b0;

    auto loadA = [&](int k) {
        int kk = kbase + k + akoff;
        long row = row0 + arow;
        const float* p;
        if (A1) p = (kk < 128) ? (A0 + row * 128 + kk)
                               : (A1 + row * 128 + (kk - 128));
        else    p = A0 + row * (long)K + kk;
        a0 = *(const float4*)p;
        a1 = *(const float4*)(p + 4);
    };
    auto loadB = [&](int k) { b0 = *(const float4*)(Bp + k); };
    auto stAB = [&](int buf) {
        As[buf][akoff + 0][arow] = a0.x; As[buf][akoff + 1][arow] = a0.y;
        As[buf][akoff + 2][arow] = a0.z; As[buf][akoff + 3][arow] = a0.w;
        As[buf][akoff + 4][arow] = a1.x; As[buf][akoff + 5][arow] = a1.y;
        As[buf][akoff + 6][arow] = a1.z; As[buf][akoff + 7][arow] = a1.w;
        Bs[buf][bkoff + 0][brow] = b0.x; Bs[buf][bkoff + 1][brow] = b0.y;
        Bs[buf][bkoff + 2][brow] = b0.z; Bs[buf][bkoff + 3][brow] = b0.w;
    };

    loadA(0); loadB(0);
    stAB(0);
    __syncthreads();

    int buf = 0;
    for (int k0 = 0; k0 < Kslice; k0 += 16) {
        const bool nxt = (k0 + 16) < Kslice;
        if (nxt) { loadA(k0 + 16); loadB(k0 + 16); }
        #pragma unroll
        for (int kk = 0; kk < 16; kk++) {
            ull rap[4];
            *(float4*)(&rap[0]) = *(const float4*)&As[buf][kk][tr];
            *(float4*)(&rap[2]) = *(const float4*)&As[buf][kk][tr + 4];
            float4 rbv = *(const float4*)&Bs[buf][kk][tc];
            ull bd0 = dupf(rbv.x), bd1 = dupf(rbv.y);
            ull bd2 = dupf(rbv.z), bd3 = dupf(rbv.w);
            #pragma unroll
            for (int p = 0; p < 4; p++) {
                FFMA2(accp[p][0], rap[p], bd0);
                FFMA2(accp[p][1], rap[p], bd1);
                FFMA2(accp[p][2], rap[p], bd2);
                FFMA2(accp[p][3], rap[p], bd3);
            }
        }
        if (nxt) {
            buf ^= 1;
            stAB(buf);
            __syncthreads();
        }
    }

    #pragma unroll
    for (int p = 0; p < 4; p++) {
        long r0r = row0 + tr + 2 * p;
        float o0[4], o1[4];
        #pragma unroll
        for (int j = 0; j < 4; j++) {
            o0[j] = lo32(accp[p][j]);
            o1[j] = hi32(accp[p][j]);
        }
        *(float4*)(Cz + r0r * N + col0 + tc)       = *(float4*)(o0);
        *(float4*)(Cz + (r0r + 1) * N + col0 + tc) = *(float4*)(o1);
    }
}

// ---------------------------------------------------------------------------
// fp32 NT GEMM: 128x128 tile, BK=16, 256 threads, 8x8 micro, FFMA2,
// single-buffered, occ-2, conflict-free B reads (16B lane stride).
// Concat mode via A1. Split-K via gridDim.z.
// ---------------------------------------------------------------------------
__global__ void __launch_bounds__(256, 2)
gemm_nt_128x128(const float* __restrict__ A0, const float* __restrict__ A1,
                const float* __restrict__ B, float* __restrict__ C,
                int M, int N, int K)
{
    __shared__ float As[16][128];
    __shared__ float Bs[16][128];
    const int tid  = threadIdx.x;
    const int row0 = blockIdx.y * 128;
    const int col0 = blockIdx.x * 128;
    const int Kslice = K / gridDim.z;
    const int kbase  = blockIdx.z * Kslice;
    float* Cz = C + (size_t)blockIdx.z * (size_t)M * N;

    const int lrow = tid >> 1;
    const int koff = (tid & 1) << 3;
    const int tr = (tid >> 4) << 3;
    const int tc = (tid & 15) << 2;      // 16B stride: conflict-free

    ull accp[4][8] = {};   // j 0-3: cols tc+j ; j 4-7: cols 64+tc+(j-4)

    const float* Bp = B + (long)(col0 + lrow) * K + kbase + koff;
    const long arowg = row0 + lrow;

    for (int k0 = 0; k0 < Kslice; k0 += 16) {
        float4 a0, a1, b0, b1;
        {
            int kk = kbase + k0 + koff;
            const float* p;
            if (A1) p = (kk < 128) ? (A0 + arowg * 128 + kk)
                                   : (A1 + arowg * 128 + (kk - 128));
            else    p = A0 + arowg * (long)K + kk;
            a0 = *(const float4*)p;
            a1 = *(const float4*)(p + 4);
            b0 = *(const float4*)(Bp + k0);
            b1 = *(const float4*)(Bp + k0 + 4);
        }
        __syncthreads();
        As[koff + 0][lrow] = a0.x; As[koff + 1][lrow] = a0.y;
        As[koff + 2][lrow] = a0.z; As[koff + 3][lrow] = a0.w;
        As[koff + 4][lrow] = a1.x; As[koff + 5][lrow] = a1.y;
        As[koff + 6][lrow] = a1.z; As[koff + 7][lrow] = a1.w;
        Bs[koff + 0][lrow] = b0.x; Bs[koff + 1][lrow] = b0.y;
        Bs[koff + 2][lrow] = b0.z; Bs[koff + 3][lrow] = b0.w;
        Bs[koff + 4][lrow] = b1.x; Bs[koff + 5][lrow] = b1.y;
        Bs[koff + 6][lrow] = b1.z; Bs[koff + 7][lrow] = b1.w;
        __syncthreads();

        #pragma unroll
        for (int kk = 0; kk < 16; kk++) {
            ull rap[4];
            *(float4*)(&rap[0]) = *(const float4*)&As[kk][tr];
            *(float4*)(&rap[2]) = *(const float4*)&As[kk][tr + 4];
            {
                float4 rb = *(const float4*)&Bs[kk][tc];
                ull bd0 = dupf(rb.x), bd1 = dupf(rb.y);
                ull bd2 = dupf(rb.z), bd3 = dupf(rb.w);
                #pragma unroll
                for (int p = 0; p < 4; p++) {
                    FFMA2(accp[p][0], rap[p], bd0);
                    FFMA2(accp[p][1], rap[p], bd1);
                    FFMA2(accp[p][2], rap[p], bd2);
                    FFMA2(accp[p][3], rap[p], bd3);
                }
            }
            {
                float4 rb = *(const float4*)&Bs[kk][64 + tc];
                ull bd0 = dupf(rb.x), bd1 = dupf(rb.y);
                ull bd2 = dupf(rb.z), bd3 = dupf(rb.w);
                #pragma unroll
                for (int p = 0; p < 4; p++) {
                    FFMA2(accp[p][4], rap[p], bd0);
                    FFMA2(accp[p][5], rap[p], bd1);
                    FFMA2(accp[p][6], rap[p], bd2);
                    FFMA2(accp[p][7], rap[p], bd3);
                }
            }
        }
    }

    #pragma unroll
    for (int p = 0; p < 4; p++) {
        long r0r = row0 + tr + 2 * p;
        float o0a[4], o1a[4], o0b[4], o1b[4];
        #pragma unroll
        for (int j = 0; j < 4; j++) {
            o0a[j] = lo32(accp[p][j]);
            o1a[j] = hi32(accp[p][j]);
            o0b[j] = lo32(accp[p][4 + j]);
            o1b[j] = hi32(accp[p][4 + j]);
        }
        *(float4*)(Cz + r0r * N + col0 + tc)            = *(float4*)(o0a);
        *(float4*)(Cz + r0r * N + col0 + 64 + tc)       = *(float4*)(o0b);
        *(float4*)(Cz + (r0r + 1) * N + col0 + tc)      = *(float4*)(o1a);
        *(float4*)(Cz + (r0r + 1) * N + col0 + 64 + tc) = *(float4*)(o1b);
    }
}

// ---------------------------------------------------------------------------
// Small fp32 NT GEMM (64x64, 4x4, FFMA2) with A-combine mode.
// ---------------------------------------------------------------------------
__global__ void gemm_nt_64(const float* __restrict__ A,
                           int nslabs, size_t slabStride,
                           const float* __restrict__ ab,
                           const float* __restrict__ B,
                           const float* __restrict__ bias,
                           float* __restrict__ C,
                           int M, int N, int K)
{
    __shared__ float As[16][64];
    __shared__ float Bs[16][64];
    int tid = threadIdx.x;
    int row0 = blockIdx.y * 64;
    int col0 = blockIdx.x * 64;

    int lr = tid >> 2;
    int lk = (tid & 3) << 2;
    int tr = tid >> 4;
    int tc = tid & 15;
    ull accp[2][4] = {};
    const float* Ap = A + (long)(row0 + lr) * K + lk;
    const float* Bp = B + (long)(col0 + lr) * K + lk;
    for (int k0 = 0; k0 < K; k0 += 16) {
        float4 a = *(const float4*)(Ap + k0);
        if (nslabs > 1) {
            #pragma unroll 3
            for (int z = 1; z < nslabs; z++) {
                float4 a2 = *(const float4*)(Ap + z * slabStride + k0);
                a.x += a2.x; a.y += a2.y; a.z += a2.z; a.w += a2.w;
            }
            float4 av = *(const float4*)(ab + lk + k0);
            a.x = fmaxf(a.x + av.x, 0.f);
            a.y = fmaxf(a.y + av.y, 0.f);
            a.z = fmaxf(a.z + av.z, 0.f);
            a.w = fmaxf(a.w + av.w, 0.f);
        }
        float4 bq = *(const float4*)(Bp + k0);
        As[lk + 0][lr] = a.x;  As[lk + 1][lr] = a.y;
        As[lk + 2][lr] = a.z;  As[lk + 3][lr] = a.w;
        Bs[lk + 0][lr] = bq.x; Bs[lk + 1][lr] = bq.y;
        Bs[lk + 2][lr] = bq.z; Bs[lk + 3][lr] = bq.w;
        __syncthreads();
        #pragma unroll
        for (int kk = 0; kk < 16; kk++) {
            ull rap[2];
            *(float4*)(&rap[0]) = *(const float4*)&As[kk][tr * 4];
            float4 rbv = *(const float4*)&Bs[kk][tc * 4];
            ull bd0 = dupf(rbv.x);
            ull bd1 = dupf(rbv.y);
            ull bd2 = dupf(rbv.z);
            ull bd3 = dupf(rbv.w);
            #pragma unroll
            for (int p = 0; p < 2; p++) {
                FFMA2(accp[p][0], rap[p], bd0);
                FFMA2(accp[p][1], rap[p], bd1);
                FFMA2(accp[p][2], rap[p], bd2);
                FFMA2(accp[p][3], rap[p], bd3);
            }
        }
        __syncthreads();
    }
    #pragma unroll
    for (int p = 0; p < 2; p++) {
        long r0r = row0 + tr * 4 + 2 * p;
        #pragma unroll
        for (int j = 0; j < 4; j++) {
            int c = col0 + tc * 4 + j;
            float v0 = lo32(accp[p][j]);
            float v1 = hi32(accp[p][j]);
            if (bias) { v0 += bias[c]; v1 += bias[c]; }
            C[r0r * N + c]       = v0;
            C[(r0r + 1) * N + c] = v1;
        }
    }
}

// ---------------------------------------------------------------------------
// Flash attention: 1 warp per batch, zero smem, single pass over k0.
// Sums 2 qk slabs in q-load. Register-double-buffered token prefetch:
// token n+1's k-rows load while token n is processed (manual 2x unroll,
// A/B buffers are distinct registers so no copies).
// ---------------------------------------------------------------------------
__global__ void __launch_bounds__(128)
attn_flash_kernel(const float* __restrict__ seq,
                  const float* __restrict__ seq_e,
                  const float* __restrict__ seq_t,
                  const int* __restrict__ mask,
                  const float* __restrict__ qk,
                  float* __restrict__ ctx,
                  float* __restrict__ attn_out)
{
    const int lane = threadIdx.x & 31;
    const long b = (long)blockIdx.x * 4 + (threadIdx.x >> 5);

    ull q0p[6], q1p[6];
    {
        const float* qp  = qk + b * 768 + lane * 4;
        const float* qp2 = qp + (size_t)Bsz * 768;
        #pragma unroll
        for (int it = 0; it < 3; it++) {
            float4 u = *(const float4*)(qp + it * 128);
            float4 v = *(const float4*)(qp2 + it * 128);
            float4 s = make_float4(u.x + v.x, u.y + v.y, u.z + v.z, u.w + v.w);
            *(float4*)(&q0p[it * 2]) = s;
            u = *(const float4*)(qp + 384 + it * 128);
            v = *(const float4*)(qp2 + 384 + it * 128);
            s = make_float4(u.x + v.x, u.y + v.y, u.z + v.z, u.w + v.w);
            *(float4*)(&q1p[it * 2]) = s;
        }
    }

    ull c0p[6] = {}, c1p[6] = {};
    float m0 = -1e30f, m1 = -1e30f, l0 = 0.f, l1 = 0.f;
    float lg0[2], lg1[2];

    const float* p0 = seq   + b * 64 * 128 + lane * 4;
    const float* p1 = seq_e + b * 64 * 128 + lane * 4;
    const float* p2 = seq_t + b * 64 * 128 + lane * 4;
    const int*   mp = mask + b * 64;

    const float SCALE = 0.07216878364870323f;   // 1/sqrt(192)

    // one token's full update, given its k-rows already in registers
    auto process = [&](const ull* kp, int n) {
        int mk = mp[n];
        ull s0p = 0, s1p = 0;
        #pragma unroll
        for (int j = 0; j < 6; j++) {
            FFMA2(s0p, kp[j], q0p[j]);
            FFMA2(s1p, kp[j], q1p[j]);
        }
        float s0 = lo32(s0p) + hi32(s0p);
        float s1 = lo32(s1p) + hi32(s1p);
        #pragma unroll
        for (int o = 16; o; o >>= 1) {
            s0 += __shfl_xor_sync(0xffffffffu, s0, o);
            s1 += __shfl_xor_sync(0xffffffffu, s1, o);
        }
        s0 *= SCALE;
        s1 *= SCALE;
        if (mk != 0) { s0 = -1e10f; s1 = -1e10f; }
        if ((n & 31) == lane) {
            lg0[n >> 5] = s0;
            lg1[n >> 5] = s1;
        }
        float nm0 = fmaxf(m0, s0);
        float r0  = __expf(m0 - nm0);
        float e0  = __expf(s0 - nm0);
        m0 = nm0;
        l0 = fmaf(l0, r0, e0);
        {
            ull rd = dupf(r0), ed = dupf(e0);
            #pragma unroll
            for (int j = 0; j < 6; j++) {
                MUL2(c0p[j], c0p[j], rd);
                FFMA2(c0p[j], ed, kp[j]);
            }
        }
        float nm1 = fmaxf(m1, s1);
        float r1  = __expf(m1 - nm1);
        float e1  = __expf(s1 - nm1);
        m1 = nm1;
        l1 = fmaf(l1, r1, e1);
        {
            ull rd = dupf(r1), ed = dupf(e1);
            #pragma unroll
            for (int j = 0; j < 6; j++) {
                MUL2(c1p[j], c1p[j], rd);
                FFMA2(c1p[j], ed, kp[j]);
            }
        }
    };

    ull kpA[6], kpB[6];
    // preload token 0
    *(float4*)(&kpA[0]) = *(const float4*)(p0);
    *(float4*)(&kpA[2]) = *(const float4*)(p1);
    *(float4*)(&kpA[4]) = *(const float4*)(p2);

    #pragma unroll 2
    for (int n = 0; n < 64; n += 2) {
        // prefetch token n+1 while processing n
        *(float4*)(&kpB[0]) = *(const float4*)(p0 + (n + 1) * 128);
        *(float4*)(&kpB[2]) = *(const float4*)(p1 + (n + 1) * 128);
        *(float4*)(&kpB[4]) = *(const float4*)(p2 + (n + 1) * 128);
        process(kpA, n);
        // prefetch token n+2 while processing n+1
        if (n + 2 < 64) {
            *(float4*)(&kpA[0]) = *(const float4*)(p0 + (n + 2) * 128);
            *(float4*)(&kpA[2]) = *(const float4*)(p1 + (n + 2) * 128);
            *(float4*)(&kpA[4]) = *(const float4*)(p2 + (n + 2) * 128);
        }
        process(kpB, n + 1);
    }

    const float inv0 = 1.f / l0;
    const float inv1 = 1.f / l1;

    {
        float* cp = ctx + b * 768 + lane * 4;
        #pragma unroll
        for (int it = 0; it < 3; it++) {
            float o0[4], o1[4];
            o0[0] = lo32(c0p[it*2])   * inv0; o0[1] = hi32(c0p[it*2])   * inv0;
            o0[2] = lo32(c0p[it*2+1]) * inv0; o0[3] = hi32(c0p[it*2+1]) * inv0;
            o1[0] = lo32(c1p[it*2])   * inv1; o1[1] = hi32(c1p[it*2])   * inv1;
            o1[2] = lo32(c1p[it*2+1]) * inv1; o1[3] = hi32(c1p[it*2+1]) * inv1;
            *(float4*)(cp + it * 128)       = *(float4*)(o0);
            *(float4*)(cp + 384 + it * 128) = *(float4*)(o1);
        }
    }

    attn_out[b * 64 + lane]                     = __expf(lg0[0] - m0) * inv0;
    attn_out[b * 64 + 32 + lane]                = __expf(lg0[1] - m0) * inv0;
    attn_out[((long)Bsz + b) * 64 + lane]       = __expf(lg1[0] - m1) * inv1;
    attn_out[((long)Bsz + b) * 64 + 32 + lane]  = __expf(lg1[1] - m1) * inv1;
}

// ---------------------------------------------------------------------------
// res = 3 out-slabs + bo + q0 ; LayerNorm(384) ; x = [ln_out | src]
// ---------------------------------------------------------------------------
__global__ void ln_kernel(const float* __restrict__ outp,
                          const float* __restrict__ bo,
                          const float* __restrict__ src,
                          const float* __restrict__ src_t,
                          const float* __restrict__ g,
                          const float* __restrict__ bta,
                          float* __restrict__ x)
{
    const size_t SLAB = (size_t)Bsz * 384;
    int wid = threadIdx.x >> 5, lane = threadIdx.x & 31;
    long b = (long)blockIdx.x * 8 + wid;
    float r[12];
    float sum = 0.f, sq = 0.f;
    #pragma unroll
    for (int i = 0; i < 12; i++) {
        int m = lane + i * 32;
        size_t idx = b * 384 + m;
        float v = outp[idx] + outp[idx + SLAB] + outp[idx + 2 * SLAB] + bo[m];
        if (i < 4)       v += src[b * 128 + m];
        else if (i >= 8) v += src_t[b * 128 + (m - 256)];
        r[i] = v;
        sum += v;
        sq  = fmaf(v, v, sq);
    }
    #pragma unroll
    for (int o = 16; o; o >>= 1) {
        sum += __shfl_xor_sync(0xffffffffu, sum, o);
        sq  += __shfl_xor_sync(0xffffffffu, sq, o);
    }
    float mu  = sum * (1.f / 384.f);
    float var = sq * (1.f / 384.f) - mu * mu;
    float inv = rsqrtf(var + 1e-5f);
    #pragma unroll
    for (int i = 0; i < 12; i++) {
        int m = lane + i * 32;
        x[b * 512 + m] = (r[i] - mu) * inv * g[m] + bta[m];
    }
    #pragma unroll
    for (int i = 0; i < 4; i++) {
        int m = lane + i * 32;
        x[b * 512 + 384 + m] = src[b * 128 + m];
    }
}

// ---------------------------------------------------------------------------

extern "C" void kernel_launch(void* const* d_in, const int* in_sizes, int n_in,
                              void* d_out, int out_size)
{
    const float* src   = (const float*)d_in[0];
    const float* src_t = (const float*)d_in[1];
    const float* seq   = (const float*)d_in[2];
    const float* seq_t = (const float*)d_in[3];
    const float* seq_e = (const float*)d_in[4];
    const int*   mask  = (const int*)d_in[5];
    const float* Wq   = (const float*)d_in[6];
    const float* Wk   = (const float*)d_in[7];
    const float* Wv   = (const float*)d_in[8];
    const float* Wo   = (const float*)d_in[9];
    const float* bo   = (const float*)d_in[10];
    const float* ln_g = (const float*)d_in[11];
    const float* ln_b = (const float*)d_in[12];
    const float* W1   = (const float*)d_in[13];
    const float* b1   = (const float*)d_in[14];
    const float* W2   = (const float*)d_in[15];
    const float* b2   = (const float*)d_in[16];

    float* y        = (float*)d_out;
    float* attn_out = (float*)d_out + Bsz * 128;

    float *p_wqk, *p_wov, *p_qk, *p_ctx, *p_out, *p_x, *p_h;
    cudaGetSymbolAddress((void**)&p_wqk, g_wqk);
    cudaGetSymbolAddress((void**)&p_wov, g_wov);
    cudaGetSymbolAddress((void**)&p_qk,  g_qk);
    cudaGetSymbolAddress((void**)&p_ctx, g_ctx);
    cudaGetSymbolAddress((void**)&p_out, g_out);
    cudaGetSymbolAddress((void**)&p_x,   g_x);
    cudaGetSymbolAddress((void**)&p_h,   g_h);

    // 1. folds (merged, one launch)
    fold_both_kernel<<<1920, dim3(16, 16)>>>(Wk, Wq, Wo, Wv, p_wqk, p_wov);

    // 2. qk slabs = [src|src_t] @ Wqk^T   (K=256, split-K=2 -> 384 CTAs)
    gemm_nt_128x128<<<dim3(768 / 128, Bsz / 128, 2), 256>>>(
        src, src_t, p_wqk, p_qk, Bsz, 768, 256);

    // 3. flash attention (sums 2 qk slabs; token prefetch pipeline)
    attn_flash_kernel<<<Bsz / 4, 128>>>(seq, seq_e, seq_t, mask, p_qk, p_ctx, attn_out);

    // 4. out slabs = ctx @ Wov^T   (K=768, split-K=3 -> 288 CTAs) [profiled anchor]
    gemm_nt_128x128<<<dim3(384 / 128, Bsz / 128, 3), 256>>>(
        p_ctx, nullptr, p_wov, p_out, Bsz, 384, 768);

    // 5. residual (3 slabs + bo) + LN + concat
    ln_kernel<<<Bsz / 8, 256>>>(p_out, bo, src, src_t, ln_g, ln_b, p_x);

    // 6. FFN1: h slabs = x @ W1^T (K=512, split-K=4 -> 256 CTAs)
    gemm_nt_128x64<<<dim3(128 / 64, Bsz / 128, 4), 256>>>(
        p_x, nullptr, W1, p_h, Bsz, 128, 512);

    // 7. FFN2: y = relu(sum_z h_z + b1) @ W2^T + b2   (4-slab A-combine)
    gemm_nt_64<<<dim3(2, Bsz / 64), 256>>>(p_h, 4, (size_t)Bsz * 128, b1,
                                           W2, b2, y, Bsz, 128, 128);
}